// round 3
// baseline (speedup 1.0000x reference)
#include <cuda_runtime.h>
#include <math.h>

#define BB    64
#define NPT   256
#define CHANS 3
#define PPX   16
#define HH    8
#define CC    768
#define HIDD  1536
#define HDIM  96
#define LLAY  5
#define BN_   (BB*NPT)      // 16384
#define BH_   (BB*HH)       // 512
#define EPSV  1e-5f
#define SCL   0.1020620726159657f   // 96^-0.5

// ---------------- scratch (device globals; no allocation) ----------------
__device__ float  g_x   [BN_*CC];
__device__ float  g_q   [BH_*NPT*HDIM];
__device__ float  g_k   [BH_*NPT*HDIM];
__device__ float  g_v   [BH_*NPT*HDIM];
__device__ float  g_attn[BH_*NPT*NPT];     // 33.55M floats
__device__ float  g_o   [BN_*CC];
__device__ float  g_y   [BN_*CC];
__device__ float  g_h   [BN_*HIDD];
__device__ double g_bnstat[16*8];          // padded: sum h*8, sumsq (8+h)*8
__device__ float  g_bnab [2*HH];           // alpha[h], beta[h]

// ---------------- kernels ----------------

// 3x3 SAME conv (3->3 ch) on each token image, q/k/v at once. Writes [B,H,N,HD].
__global__ void k_conv(const float* __restrict__ x,
                       const float* __restrict__ qw, const float* __restrict__ qb,
                       const float* __restrict__ kw, const float* __restrict__ kb,
                       const float* __restrict__ vw, const float* __restrict__ vb,
                       float* __restrict__ q, float* __restrict__ k, float* __restrict__ v)
{
    __shared__ float xt[CHANS][PPX][PPX];
    __shared__ float wq[81], wk[81], wv[81];
    int token = blockIdx.x;            // b*NPT+n
    int b = token / NPT, n = token % NPT;
    int t = threadIdx.x;               // 256
    for (int i = t; i < CHANS*PPX*PPX; i += 256)
        ((float*)xt)[i] = x[token*CC + i];
    if (t < 81) { wq[t] = qw[t]; wk[t] = kw[t]; wv[t] = vw[t]; }
    __syncthreads();
    int py = t / PPX, px = t % PPX;
    for (int o = 0; o < CHANS; o++) {
        float aq = qb[o], ak = kb[o], av = vb[o];
        #pragma unroll
        for (int i = 0; i < CHANS; i++) {
            #pragma unroll
            for (int dy = 0; dy < 3; dy++) {
                int yy = py + dy - 1;
                if (yy < 0 || yy >= PPX) continue;
                #pragma unroll
                for (int dx = 0; dx < 3; dx++) {
                    int xx = px + dx - 1;
                    if (xx < 0 || xx >= PPX) continue;
                    float xv = xt[i][yy][xx];
                    int wi = ((o*CHANS + i)*3 + dy)*3 + dx;
                    aq += xv * wq[wi];
                    ak += xv * wk[wi];
                    av += xv * wv[wi];
                }
            }
        }
        int f = o*256 + t;
        int h = f / HDIM, d = f % HDIM;
        int idx = ((b*HH + h)*NPT + n)*HDIM + d;
        q[idx] = aq; k[idx] = ak; v[idx] = av;
    }
}

// Fused QK^T * scale + row softmax. grid (N/16, BH), 256 threads.
__global__ void k_qk_softmax(const float* __restrict__ q, const float* __restrict__ k,
                             float* __restrict__ attn)
{
    __shared__ float Ks[256][17];
    __shared__ float Qs[16*HDIM];
    int bh = blockIdx.y;
    int r0 = blockIdx.x * 16;
    int t = threadIdx.x, w = t >> 5, l = t & 31;
    const float* Kb = k + bh*NPT*HDIM;
    const float* Qb = q + (bh*NPT + r0)*HDIM;
    for (int i = t; i < 16*HDIM; i += 256) Qs[i] = Qb[i];

    float s0[8], s1[8];
    #pragma unroll
    for (int j = 0; j < 8; j++) { s0[j] = 0.f; s1[j] = 0.f; }
    int row0 = 2*w, row1 = 2*w + 1;

    for (int d0 = 0; d0 < HDIM; d0 += 16) {
        __syncthreads();
        #pragma unroll
        for (int j = 0; j < 4; j++) {
            int i4 = t + 256*j;
            int r = i4 >> 2, c4 = i4 & 3;
            float4 vv = *(const float4*)&Kb[r*HDIM + d0 + c4*4];
            Ks[r][c4*4+0] = vv.x; Ks[r][c4*4+1] = vv.y;
            Ks[r][c4*4+2] = vv.z; Ks[r][c4*4+3] = vv.w;
        }
        __syncthreads();
        #pragma unroll
        for (int dd = 0; dd < 16; dd++) {
            float q0 = Qs[row0*HDIM + d0 + dd];
            float q1 = Qs[row1*HDIM + d0 + dd];
            #pragma unroll
            for (int j = 0; j < 8; j++) {
                float kv = Ks[l + 32*j][dd];
                s0[j] += q0*kv; s1[j] += q1*kv;
            }
        }
    }
    float m0 = -1e30f, m1 = -1e30f;
    #pragma unroll
    for (int j = 0; j < 8; j++) {
        s0[j] *= SCL; s1[j] *= SCL;
        m0 = fmaxf(m0, s0[j]); m1 = fmaxf(m1, s1[j]);
    }
    #pragma unroll
    for (int off = 16; off; off >>= 1) {
        m0 = fmaxf(m0, __shfl_xor_sync(0xffffffffu, m0, off));
        m1 = fmaxf(m1, __shfl_xor_sync(0xffffffffu, m1, off));
    }
    float sum0 = 0.f, sum1 = 0.f;
    #pragma unroll
    for (int j = 0; j < 8; j++) {
        s0[j] = expf(s0[j] - m0); sum0 += s0[j];
        s1[j] = expf(s1[j] - m1); sum1 += s1[j];
    }
    #pragma unroll
    for (int off = 16; off; off >>= 1) {
        sum0 += __shfl_xor_sync(0xffffffffu, sum0, off);
        sum1 += __shfl_xor_sync(0xffffffffu, sum1, off);
    }
    float inv0 = 1.f / sum0, inv1 = 1.f / sum1;
    float* a0 = attn + (bh*NPT + r0 + row0)*NPT;
    float* a1 = attn + (bh*NPT + r0 + row1)*NPT;
    #pragma unroll
    for (int j = 0; j < 8; j++) {
        a0[l + 32*j] = s0[j]*inv0;
        a1[l + 32*j] = s1[j]*inv1;
    }
}

__global__ void k_zero_stat(double* __restrict__ stat)
{
    int t = threadIdx.x;
    if (t < 16*8) stat[t] = 0.0;
}

// Re-attention (head mixing, in place) + BN batch-stat accumulation (double).
__global__ void k_reatten(float* __restrict__ attn, const float* __restrict__ rw,
                          const float* __restrict__ rb, double* __restrict__ stat)
{
    __shared__ double sacc[16];
    int t = threadIdx.x;
    if (t < 16) sacc[t] = 0.0;
    __syncthreads();
    int idx = blockIdx.x*256 + t;                 // over B*N*N = 4.19M
    int b  = idx >> 16;                           // N*N = 65536
    int nm = idx & 65535;
    int base = b*HH*65536 + nm;
    float a[HH];
    #pragma unroll
    for (int h = 0; h < HH; h++) a[h] = attn[base + h*65536];
    float out[HH];
    #pragma unroll
    for (int o = 0; o < HH; o++) {
        float s = rb[o];
        #pragma unroll
        for (int i = 0; i < HH; i++) s += rw[o*HH + i] * a[i];
        out[o] = s;
    }
    #pragma unroll
    for (int h = 0; h < HH; h++) attn[base + h*65536] = out[h];
    #pragma unroll
    for (int h = 0; h < HH; h++) {
        double s = (double)out[h];
        double qq = s*s;
        #pragma unroll
        for (int off = 16; off; off >>= 1) {
            s  += __shfl_xor_sync(0xffffffffu, s, off);
            qq += __shfl_xor_sync(0xffffffffu, qq, off);
        }
        if ((t & 31) == 0) { atomicAdd(&sacc[h], s); atomicAdd(&sacc[8+h], qq); }
    }
    __syncthreads();
    if (t < 16) atomicAdd(&stat[t*8], sacc[t]);
}

__global__ void k_bnfinal(const double* __restrict__ stat, const float* __restrict__ bg,
                          const float* __restrict__ bb_, float* __restrict__ ab)
{
    int h = threadIdx.x;
    if (h >= HH) return;
    const double cnt = (double)BB * (double)NPT * (double)NPT;
    double mu  = stat[h*8] / cnt;
    double var = stat[(8+h)*8] / cnt - mu*mu;
    float  al  = (float)(rsqrt(var + (double)EPSV) * (double)bg[h]);
    ab[h]      = al;
    ab[HH + h] = bb_[h] - (float)mu * al;
}

// O = (alpha*attnR+beta) @ V (element-wise BN applied at load, matching reference
// operation order exactly); writes [B,N,C]. grid (N/64, BH), 256 threads.
__global__ void k_av(const float* __restrict__ attn, const float* __restrict__ v,
                     const float* __restrict__ ab, float* __restrict__ o)
{
    __shared__ float As[64][33];
    __shared__ float Vs[32][96];
    int bh = blockIdx.y;
    int n0 = blockIdx.x * 64;
    int t = threadIdx.x;
    int tx = t & 31, ty = t >> 5;
    int b = bh / HH, h = bh % HH;
    float alpha = ab[h], beta = ab[HH + h];
    float acc[8][3];
    #pragma unroll
    for (int i = 0; i < 8; i++) { acc[i][0] = 0.f; acc[i][1] = 0.f; acc[i][2] = 0.f; }
    const float* Ab = attn + (bh*NPT + n0)*NPT;
    const float* Vb = v + bh*NPT*HDIM;

    for (int k0 = 0; k0 < NPT; k0 += 32) {
        #pragma unroll
        for (int j = 0; j < 2; j++) {
            int i4 = t + 256*j;
            int r = i4 >> 3, c4 = i4 & 7;
            float4 vv = *(const float4*)&Ab[r*NPT + k0 + c4*4];
            As[r][c4*4+0] = alpha*vv.x + beta;
            As[r][c4*4+1] = alpha*vv.y + beta;
            As[r][c4*4+2] = alpha*vv.z + beta;
            As[r][c4*4+3] = alpha*vv.w + beta;
        }
        #pragma unroll
        for (int j = 0; j < 12; j++) {
            int i = t + 256*j;
            int r = i / 96, c = i % 96;
            Vs[r][c] = Vb[(k0 + r)*HDIM + c];
        }
        __syncthreads();
        #pragma unroll
        for (int kk = 0; kk < 32; kk++) {
            float v0 = Vs[kk][3*tx], v1 = Vs[kk][3*tx+1], v2 = Vs[kk][3*tx+2];
            #pragma unroll
            for (int i = 0; i < 8; i++) {
                float a = As[ty*8 + i][kk];
                acc[i][0] += a*v0; acc[i][1] += a*v1; acc[i][2] += a*v2;
            }
        }
        __syncthreads();
    }
    #pragma unroll
    for (int i = 0; i < 8; i++) {
        int gn = n0 + ty*8 + i;
        float* op = o + (b*NPT + gn)*CC + h*HDIM + 3*tx;
        op[0] = acc[i][0];
        op[1] = acc[i][1];
        op[2] = acc[i][2];
    }
}

// Generic SGEMM C[M,N] = A[M,K] @ B[K,N] (+epilogue).
// EPI 0: gelu(acc+bias)  EPI 1: acc+bias+res
template<int EPI>
__global__ void k_sgemm(const float* __restrict__ A, const float* __restrict__ Bm,
                        const float* __restrict__ bias, const float* __restrict__ res,
                        float* __restrict__ C, int K, int Nn)
{
    __shared__ float As[16][132];
    __shared__ float Bs[16][64];
    int m0 = blockIdx.y * 128, n0 = blockIdx.x * 64;
    int t = threadIdx.x;
    int tx = t & 15, ty = t >> 4;
    float acc[8][4];
    #pragma unroll
    for (int i = 0; i < 8; i++)
        #pragma unroll
        for (int j = 0; j < 4; j++) acc[i][j] = 0.f;

    for (int k0 = 0; k0 < K; k0 += 16) {
        #pragma unroll
        for (int j = 0; j < 2; j++) {
            int i4 = t + 256*j;
            int m = i4 >> 2, k4 = i4 & 3;
            float4 vv = *(const float4*)&A[(m0 + m)*K + k0 + k4*4];
            As[k4*4+0][m] = vv.x; As[k4*4+1][m] = vv.y;
            As[k4*4+2][m] = vv.z; As[k4*4+3][m] = vv.w;
        }
        {
            int kk = t >> 4, n4 = t & 15;
            float4 vv = *(const float4*)&Bm[(k0 + kk)*Nn + n0 + n4*4];
            *(float4*)&Bs[kk][n4*4] = vv;
        }
        __syncthreads();
        #pragma unroll
        for (int kk = 0; kk < 16; kk++) {
            float a[8];
            #pragma unroll
            for (int i = 0; i < 8; i++) a[i] = As[kk][ty*8 + i];
            float4 b4 = *(float4*)&Bs[kk][tx*4];
            #pragma unroll
            for (int i = 0; i < 8; i++) {
                acc[i][0] += a[i]*b4.x; acc[i][1] += a[i]*b4.y;
                acc[i][2] += a[i]*b4.z; acc[i][3] += a[i]*b4.w;
            }
        }
        __syncthreads();
    }
    int n = n0 + tx*4;
    float4 bv = *(const float4*)&bias[n];
    #pragma unroll
    for (int i = 0; i < 8; i++) {
        int m = m0 + ty*8 + i;
        float r0 = acc[i][0] + bv.x;
        float r1 = acc[i][1] + bv.y;
        float r2 = acc[i][2] + bv.z;
        float r3 = acc[i][3] + bv.w;
        if (EPI == 0) {
            r0 = 0.5f*r0*(1.f + erff(r0*0.7071067811865476f));
            r1 = 0.5f*r1*(1.f + erff(r1*0.7071067811865476f));
            r2 = 0.5f*r2*(1.f + erff(r2*0.7071067811865476f));
            r3 = 0.5f*r3*(1.f + erff(r3*0.7071067811865476f));
        } else {
            float4 rr = *(const float4*)&res[m*Nn + n];
            r0 += rr.x; r1 += rr.y; r2 += rr.z; r3 += rr.w;
        }
        float4 ov = make_float4(r0, r1, r2, r3);
        *(float4*)&C[m*Nn + n] = ov;
    }
}

// LayerNorm over (N,C) per batch element; double-precision statistics.
__global__ void k_ln2d(const float* __restrict__ y, const float* __restrict__ g,
                       const float* __restrict__ be, float* __restrict__ xout)
{
    __shared__ double ws[32], wq[32];
    __shared__ float mv[2];
    int b = blockIdx.x;
    const float* yb = y + b*NPT*CC;
    float* xb = xout + b*NPT*CC;
    int t = threadIdx.x;                   // 1024
    double s = 0.0, q = 0.0;
    for (int i = t; i < NPT*CC; i += 1024) { double v = (double)yb[i]; s += v; q += v*v; }
    #pragma unroll
    for (int off = 16; off; off >>= 1) {
        s += __shfl_xor_sync(0xffffffffu, s, off);
        q += __shfl_xor_sync(0xffffffffu, q, off);
    }
    if ((t & 31) == 0) { ws[t >> 5] = s; wq[t >> 5] = q; }
    __syncthreads();
    if (t < 32) {
        s = ws[t]; q = wq[t];
        #pragma unroll
        for (int off = 16; off; off >>= 1) {
            s += __shfl_xor_sync(0xffffffffu, s, off);
            q += __shfl_xor_sync(0xffffffffu, q, off);
        }
        if (t == 0) {
            const double cnt = (double)(NPT*CC);
            double mu = s / cnt;
            double var = q / cnt - mu*mu;
            mv[0] = (float)mu; mv[1] = (float)rsqrt(var + (double)EPSV);
        }
    }
    __syncthreads();
    float mu = mv[0], rs = mv[1];
    for (int i = t; i < NPT*CC; i += 1024)
        xb[i] = (yb[i] - mu)*rs*g[i] + be[i];
}

// ---------------- host ----------------
extern "C" void kernel_launch(void* const* d_in, const int* in_sizes, int n_in,
                              void* d_out, int out_size)
{
    (void)in_sizes; (void)n_in; (void)out_size;
    const float* x_in  = (const float*)d_in[0];
    const float* qw    = (const float*)d_in[1];
    const float* qb    = (const float*)d_in[2];
    const float* kw    = (const float*)d_in[3];
    const float* kb    = (const float*)d_in[4];
    const float* vw    = (const float*)d_in[5];
    const float* vb    = (const float*)d_in[6];
    const float* rw    = (const float*)d_in[7];
    const float* rb    = (const float*)d_in[8];
    const float* bng   = (const float*)d_in[9];
    const float* bnb   = (const float*)d_in[10];
    const float* pw    = (const float*)d_in[11];
    const float* pb    = (const float*)d_in[12];
    const float* l1g   = (const float*)d_in[13];
    const float* l1b   = (const float*)d_in[14];
    const float* w1    = (const float*)d_in[15];
    const float* b1    = (const float*)d_in[16];
    const float* w2    = (const float*)d_in[17];
    const float* b2    = (const float*)d_in[18];
    const float* l2g   = (const float*)d_in[19];
    const float* l2b   = (const float*)d_in[20];

    float *px, *pq, *pk, *pv, *pa, *po, *py, *ph, *pab;
    double *pst;
    cudaGetSymbolAddress((void**)&px,  g_x);
    cudaGetSymbolAddress((void**)&pq,  g_q);
    cudaGetSymbolAddress((void**)&pk,  g_k);
    cudaGetSymbolAddress((void**)&pv,  g_v);
    cudaGetSymbolAddress((void**)&pa,  g_attn);
    cudaGetSymbolAddress((void**)&po,  g_o);
    cudaGetSymbolAddress((void**)&py,  g_y);
    cudaGetSymbolAddress((void**)&ph,  g_h);
    cudaGetSymbolAddress((void**)&pst, g_bnstat);
    cudaGetSymbolAddress((void**)&pab, g_bnab);

    for (int l = 0; l < LLAY; l++) {
        const float* xsrc = (l == 0) ? x_in : px;
        float* ln2dst = (l == LLAY-1) ? (float*)d_out : px;

        k_conv<<<BN_, 256>>>(xsrc,
                             qw + l*81, qb + l*3,
                             kw + l*81, kb + l*3,
                             vw + l*81, vb + l*3,
                             pq, pk, pv);
        k_qk_softmax<<<dim3(NPT/16, BH_), 256>>>(pq, pk, pa);
        k_zero_stat<<<1, 128>>>(pst);
        k_reatten<<<(BB*NPT*NPT)/256, 256>>>(pa, rw + l*HH*HH, rb + l*HH, pst);
        k_bnfinal<<<1, 32>>>(pst, bng + l*HH, bnb + l*HH, pab);
        k_av<<<dim3(NPT/64, BH_), 256>>>(pa, pv, pab, po);
        k_sgemm<1><<<dim3(CC/64, BN_/128), 256>>>(po, pw + l*CC*CC, pb + l*CC, xsrc, py, CC, CC);
        k_ln2d<<<BB, 1024>>>(py, l1g + l*NPT*CC, l1b + l*NPT*CC, px);
        k_sgemm<0><<<dim3(HIDD/64, BN_/128), 256>>>(px, w1 + l*CC*HIDD, b1 + l*HIDD, px, ph, CC, HIDD);
        k_sgemm<1><<<dim3(CC/64, BN_/128), 256>>>(ph, w2 + l*HIDD*CC, b2 + l*CC, px, py, HIDD, CC);
        k_ln2d<<<BB, 1024>>>(py, l2g + l*NPT*CC, l2b + l*NPT*CC, ln2dst);
    }
}

// round 5
// speedup vs baseline: 1.1258x; 1.1258x over previous
#include <cuda_runtime.h>
#include <math.h>

#define BB    64
#define NPT   256
#define CHANS 3
#define PPX   16
#define HH    8
#define CC    768
#define HIDD  1536
#define HDIM  96
#define LLAY  5
#define BN_   (BB*NPT)      // 16384
#define BH_   (BB*HH)       // 512
#define EPSV  1e-5f
#define SCL   0.1020620726159657f   // 96^-0.5

// ---------------- scratch (device globals; no allocation) ----------------
__device__ float  g_x   [BN_*CC];
__device__ float  g_q   [BH_*NPT*HDIM];
__device__ float  g_k   [BH_*NPT*HDIM];
__device__ float  g_v   [BH_*NPT*HDIM];
__device__ float  g_attn[BH_*NPT*NPT];     // 33.55M floats
__device__ float  g_o   [BN_*CC];
__device__ float  g_y   [BN_*CC];
__device__ float  g_h   [BN_*HIDD];
__device__ double g_bnstat[16*8];          // padded: sum h*8, sumsq (8+h)*8
__device__ float  g_bnab [2*HH];           // alpha[h], beta[h]

// ---------------- kernels ----------------

// 3x3 SAME conv (3->3 ch) on each token image, q/k/v at once. Writes [B,H,N,HD].
__global__ void k_conv(const float* __restrict__ x,
                       const float* __restrict__ qw, const float* __restrict__ qb,
                       const float* __restrict__ kw, const float* __restrict__ kb,
                       const float* __restrict__ vw, const float* __restrict__ vb,
                       float* __restrict__ q, float* __restrict__ k, float* __restrict__ v)
{
    __shared__ float xt[CHANS][PPX][PPX];
    __shared__ float wq[81], wk[81], wv[81];
    int token = blockIdx.x;            // b*NPT+n
    int b = token / NPT, n = token % NPT;
    int t = threadIdx.x;               // 256
    for (int i = t; i < CHANS*PPX*PPX; i += 256)
        ((float*)xt)[i] = x[token*CC + i];
    if (t < 81) { wq[t] = qw[t]; wk[t] = kw[t]; wv[t] = vw[t]; }
    __syncthreads();
    int py = t / PPX, px = t % PPX;
    for (int o = 0; o < CHANS; o++) {
        float aq = qb[o], ak = kb[o], av = vb[o];
        #pragma unroll
        for (int i = 0; i < CHANS; i++) {
            #pragma unroll
            for (int dy = 0; dy < 3; dy++) {
                int yy = py + dy - 1;
                if (yy < 0 || yy >= PPX) continue;
                #pragma unroll
                for (int dx = 0; dx < 3; dx++) {
                    int xx = px + dx - 1;
                    if (xx < 0 || xx >= PPX) continue;
                    float xv = xt[i][yy][xx];
                    int wi = ((o*CHANS + i)*3 + dy)*3 + dx;
                    aq += xv * wq[wi];
                    ak += xv * wk[wi];
                    av += xv * wv[wi];
                }
            }
        }
        int f = o*256 + t;
        int h = f / HDIM, d = f % HDIM;
        int idx = ((b*HH + h)*NPT + n)*HDIM + d;
        q[idx] = aq; k[idx] = ak; v[idx] = av;
    }
}

// Fused QK^T * scale + row softmax. grid (N/16, BH), 256 threads.
__global__ void k_qk_softmax(const float* __restrict__ q, const float* __restrict__ k,
                             float* __restrict__ attn)
{
    __shared__ float Ks[256][17];
    __shared__ float Qs[16*HDIM];
    int bh = blockIdx.y;
    int r0 = blockIdx.x * 16;
    int t = threadIdx.x, w = t >> 5, l = t & 31;
    const float* Kb = k + bh*NPT*HDIM;
    const float* Qb = q + (bh*NPT + r0)*HDIM;
    for (int i = t; i < 16*HDIM; i += 256) Qs[i] = Qb[i];

    float s0[8], s1[8];
    #pragma unroll
    for (int j = 0; j < 8; j++) { s0[j] = 0.f; s1[j] = 0.f; }
    int row0 = 2*w, row1 = 2*w + 1;

    for (int d0 = 0; d0 < HDIM; d0 += 16) {
        __syncthreads();
        #pragma unroll
        for (int j = 0; j < 4; j++) {
            int i4 = t + 256*j;
            int r = i4 >> 2, c4 = i4 & 3;
            float4 vv = *(const float4*)&Kb[r*HDIM + d0 + c4*4];
            Ks[r][c4*4+0] = vv.x; Ks[r][c4*4+1] = vv.y;
            Ks[r][c4*4+2] = vv.z; Ks[r][c4*4+3] = vv.w;
        }
        __syncthreads();
        #pragma unroll
        for (int dd = 0; dd < 16; dd++) {
            float q0 = Qs[row0*HDIM + d0 + dd];
            float q1 = Qs[row1*HDIM + d0 + dd];
            #pragma unroll
            for (int j = 0; j < 8; j++) {
                float kv = Ks[l + 32*j][dd];
                s0[j] += q0*kv; s1[j] += q1*kv;
            }
        }
    }
    float m0 = -1e30f, m1 = -1e30f;
    #pragma unroll
    for (int j = 0; j < 8; j++) {
        s0[j] *= SCL; s1[j] *= SCL;
        m0 = fmaxf(m0, s0[j]); m1 = fmaxf(m1, s1[j]);
    }
    #pragma unroll
    for (int off = 16; off; off >>= 1) {
        m0 = fmaxf(m0, __shfl_xor_sync(0xffffffffu, m0, off));
        m1 = fmaxf(m1, __shfl_xor_sync(0xffffffffu, m1, off));
    }
    float sum0 = 0.f, sum1 = 0.f;
    #pragma unroll
    for (int j = 0; j < 8; j++) {
        s0[j] = expf(s0[j] - m0); sum0 += s0[j];
        s1[j] = expf(s1[j] - m1); sum1 += s1[j];
    }
    #pragma unroll
    for (int off = 16; off; off >>= 1) {
        sum0 += __shfl_xor_sync(0xffffffffu, sum0, off);
        sum1 += __shfl_xor_sync(0xffffffffu, sum1, off);
    }
    float inv0 = 1.f / sum0, inv1 = 1.f / sum1;
    float* a0 = attn + (bh*NPT + r0 + row0)*NPT;
    float* a1 = attn + (bh*NPT + r0 + row1)*NPT;
    #pragma unroll
    for (int j = 0; j < 8; j++) {
        a0[l + 32*j] = s0[j]*inv0;
        a1[l + 32*j] = s1[j]*inv1;
    }
}

__global__ void k_zero_stat(double* __restrict__ stat)
{
    int t = threadIdx.x;
    if (t < 16*8) stat[t] = 0.0;
}

// Re-attention (head mixing, in place, float4-vectorized) + BN stats (double).
__global__ void k_reatten(float* __restrict__ attn, const float* __restrict__ rw,
                          const float* __restrict__ rb, double* __restrict__ stat)
{
    __shared__ float srw[64];
    __shared__ float srb[8];
    __shared__ double sacc[16];
    int t = threadIdx.x;
    if (t < 64) srw[t] = rw[t];
    if (t < 8)  srb[t] = rb[t];
    if (t < 16) sacc[t] = 0.0;
    __syncthreads();
    int e = (blockIdx.x*256 + t)*4;               // element idx over B*N*N = 4.19M
    int b  = e >> 16;                             // N*N = 65536
    int nm = e & 65535;
    int base = b*HH*65536 + nm;
    float4 a[HH];
    #pragma unroll
    for (int h = 0; h < HH; h++) a[h] = *(const float4*)&attn[base + h*65536];
    float4 o[HH];
    #pragma unroll
    for (int oo = 0; oo < HH; oo++) {
        float bias = srb[oo];
        float sx = bias, sy = bias, sz = bias, sw = bias;
        #pragma unroll
        for (int i = 0; i < HH; i++) {
            float w = srw[oo*HH + i];
            sx += w*a[i].x; sy += w*a[i].y; sz += w*a[i].z; sw += w*a[i].w;
        }
        o[oo] = make_float4(sx, sy, sz, sw);
    }
    #pragma unroll
    for (int h = 0; h < HH; h++) *(float4*)&attn[base + h*65536] = o[h];
    #pragma unroll
    for (int h = 0; h < HH; h++) {
        float fs = o[h].x + o[h].y + o[h].z + o[h].w;
        float fq = o[h].x*o[h].x + o[h].y*o[h].y + o[h].z*o[h].z + o[h].w*o[h].w;
        double s = (double)fs, qq = (double)fq;
        #pragma unroll
        for (int off = 16; off; off >>= 1) {
            s  += __shfl_xor_sync(0xffffffffu, s, off);
            qq += __shfl_xor_sync(0xffffffffu, qq, off);
        }
        if ((t & 31) == 0) { atomicAdd(&sacc[h], s); atomicAdd(&sacc[8+h], qq); }
    }
    __syncthreads();
    if (t < 16) atomicAdd(&stat[t*8], sacc[t]);
}

__global__ void k_bnfinal(const double* __restrict__ stat, const float* __restrict__ bg,
                          const float* __restrict__ bb_, float* __restrict__ ab)
{
    int h = threadIdx.x;
    if (h >= HH) return;
    const double cnt = (double)BB * (double)NPT * (double)NPT;
    double mu  = stat[h*8] / cnt;
    double var = stat[(8+h)*8] / cnt - mu*mu;
    float  al  = (float)(rsqrt(var + (double)EPSV) * (double)bg[h]);
    ab[h]      = al;
    ab[HH + h] = bb_[h] - (float)mu * al;
}

// O = (alpha*attnR+beta) @ V; writes [B,N,C]. grid (N/64, BH), 256 threads.
__global__ void k_av(const float* __restrict__ attn, const float* __restrict__ v,
                     const float* __restrict__ ab, float* __restrict__ o)
{
    __shared__ float As[64][33];
    __shared__ float Vs[32][96];
    int bh = blockIdx.y;
    int n0 = blockIdx.x * 64;
    int t = threadIdx.x;
    int tx = t & 31, ty = t >> 5;
    int b = bh / HH, h = bh % HH;
    float alpha = ab[h], beta = ab[HH + h];
    float acc[8][3];
    #pragma unroll
    for (int i = 0; i < 8; i++) { acc[i][0] = 0.f; acc[i][1] = 0.f; acc[i][2] = 0.f; }
    const float* Ab = attn + (bh*NPT + n0)*NPT;
    const float* Vb = v + bh*NPT*HDIM;

    for (int k0 = 0; k0 < NPT; k0 += 32) {
        #pragma unroll
        for (int j = 0; j < 2; j++) {
            int i4 = t + 256*j;
            int r = i4 >> 3, c4 = i4 & 7;
            float4 vv = *(const float4*)&Ab[r*NPT + k0 + c4*4];
            As[r][c4*4+0] = alpha*vv.x + beta;
            As[r][c4*4+1] = alpha*vv.y + beta;
            As[r][c4*4+2] = alpha*vv.z + beta;
            As[r][c4*4+3] = alpha*vv.w + beta;
        }
        #pragma unroll
        for (int j = 0; j < 12; j++) {
            int i = t + 256*j;
            int r = i / 96, c = i % 96;
            Vs[r][c] = Vb[(k0 + r)*HDIM + c];
        }
        __syncthreads();
        #pragma unroll
        for (int kk = 0; kk < 32; kk++) {
            float v0 = Vs[kk][3*tx], v1 = Vs[kk][3*tx+1], v2 = Vs[kk][3*tx+2];
            #pragma unroll
            for (int i = 0; i < 8; i++) {
                float a = As[ty*8 + i][kk];
                acc[i][0] += a*v0; acc[i][1] += a*v1; acc[i][2] += a*v2;
            }
        }
        __syncthreads();
    }
    #pragma unroll
    for (int i = 0; i < 8; i++) {
        int gn = n0 + ty*8 + i;
        float* op = o + (b*NPT + gn)*CC + h*HDIM + 3*tx;
        op[0] = acc[i][0];
        op[1] = acc[i][1];
        op[2] = acc[i][2];
    }
}

// ---------------- 3xTF32 split-precision tensor-core GEMM ----------------
// C[M,N] = A[M,K] @ B[K,N] (+epilogue). EPI 0: gelu(acc+bias)  EPI 1: acc+bias+res
// x = hi + lo (hi = tf32(x), lo = tf32(x - hi)); A*B = Ahi*Bhi + Ahi*Blo + Alo*Bhi.
// Block tile 128x128x16, 256 threads, warp tile 64x32, mma.sync.m16n8k8 tf32.
__device__ __forceinline__ unsigned f2t(float x)
{
    unsigned u;
    asm("cvt.rna.tf32.f32 %0, %1;" : "=r"(u) : "f"(x));
    return u;
}
__device__ __forceinline__ void split2(float x, unsigned& hi, unsigned& lo)
{
    hi = f2t(x);
    lo = f2t(x - __uint_as_float(hi));
}
#define MMA_TF32(ACC, A0, A1, A2, A3, B0, B1)                                 \
    asm volatile(                                                             \
        "mma.sync.aligned.m16n8k8.row.col.f32.tf32.tf32.f32 "                 \
        "{%0,%1,%2,%3}, {%4,%5,%6,%7}, {%8,%9}, {%0,%1,%2,%3};"               \
        : "+f"((ACC)[0]), "+f"((ACC)[1]), "+f"((ACC)[2]), "+f"((ACC)[3])      \
        : "r"(A0), "r"(A1), "r"(A2), "r"(A3), "r"(B0), "r"(B1))

template<int EPI>
__global__ void __launch_bounds__(256, 2)
k_tgemm(const float* __restrict__ A, const float* __restrict__ Bm,
        const float* __restrict__ bias, const float* __restrict__ res,
        float* __restrict__ C, int K, int Nn)
{
    __shared__ unsigned AsH[128][20], AsL[128][20];   // pad 20: conflict-free
    __shared__ unsigned BsH[16][136], BsL[16][136];   // pad 136: conflict-free
    int m0 = blockIdx.y * 128, n0 = blockIdx.x * 128;
    int t = threadIdx.x;
    int wid = t >> 5, l = t & 31, gid = l >> 2, tid4 = l & 3;
    int wm = (wid & 1) * 64, wn = (wid >> 1) * 32;

    float acc[4][4][4];
    #pragma unroll
    for (int mt = 0; mt < 4; mt++)
        #pragma unroll
        for (int nt = 0; nt < 4; nt++)
            #pragma unroll
            for (int r = 0; r < 4; r++) acc[mt][nt][r] = 0.f;

    for (int k0 = 0; k0 < K; k0 += 16) {
        #pragma unroll
        for (int j = 0; j < 2; j++) {            // A: 128x16 = 512 float4
            int i4 = t + 256*j;
            int r = i4 >> 2, c4 = i4 & 3;
            float4 v = *(const float4*)&A[(m0 + r)*K + k0 + c4*4];
            uint4 h, lo;
            split2(v.x, h.x, lo.x); split2(v.y, h.y, lo.y);
            split2(v.z, h.z, lo.z); split2(v.w, h.w, lo.w);
            *(uint4*)&AsH[r][c4*4] = h;
            *(uint4*)&AsL[r][c4*4] = lo;
        }
        #pragma unroll
        for (int j = 0; j < 2; j++) {            // B: 16x128 = 512 float4
            int i4 = t + 256*j;
            int r = i4 >> 5, c4 = i4 & 31;
            float4 v = *(const float4*)&Bm[(k0 + r)*Nn + n0 + c4*4];
            uint4 h, lo;
            split2(v.x, h.x, lo.x); split2(v.y, h.y, lo.y);
            split2(v.z, h.z, lo.z); split2(v.w, h.w, lo.w);
            *(uint4*)&BsH[r][c4*4] = h;
            *(uint4*)&BsL[r][c4*4] = lo;
        }
        __syncthreads();
        #pragma unroll
        for (int ks = 0; ks < 16; ks += 8) {
            unsigned bfh[4][2], bfl[4][2];
            #pragma unroll
            for (int nt = 0; nt < 4; nt++) {
                int cn = wn + nt*8 + gid;
                bfh[nt][0] = BsH[ks + tid4    ][cn];
                bfh[nt][1] = BsH[ks + tid4 + 4][cn];
                bfl[nt][0] = BsL[ks + tid4    ][cn];
                bfl[nt][1] = BsL[ks + tid4 + 4][cn];
            }
            #pragma unroll
            for (int mt = 0; mt < 4; mt++) {
                int rm = wm + mt*16;
                unsigned ah0 = AsH[rm + gid    ][ks + tid4    ];
                unsigned ah1 = AsH[rm + gid + 8][ks + tid4    ];
                unsigned ah2 = AsH[rm + gid    ][ks + tid4 + 4];
                unsigned ah3 = AsH[rm + gid + 8][ks + tid4 + 4];
                unsigned al0 = AsL[rm + gid    ][ks + tid4    ];
                unsigned al1 = AsL[rm + gid + 8][ks + tid4    ];
                unsigned al2 = AsL[rm + gid    ][ks + tid4 + 4];
                unsigned al3 = AsL[rm + gid + 8][ks + tid4 + 4];
                #pragma unroll
                for (int nt = 0; nt < 4; nt++) {
                    MMA_TF32(acc[mt][nt], ah0, ah1, ah2, ah3, bfl[nt][0], bfl[nt][1]);
                    MMA_TF32(acc[mt][nt], al0, al1, al2, al3, bfh[nt][0], bfh[nt][1]);
                    MMA_TF32(acc[mt][nt], ah0, ah1, ah2, ah3, bfh[nt][0], bfh[nt][1]);
                }
            }
        }
        __syncthreads();
    }

    #pragma unroll
    for (int mt = 0; mt < 4; mt++) {
        #pragma unroll
        for (int nt = 0; nt < 4; nt++) {
            int gm = m0 + wm + mt*16 + gid;
            int gn = n0 + wn + nt*8 + tid4*2;
            float2 bv = *(const float2*)&bias[gn];
            float r0 = acc[mt][nt][0] + bv.x;
            float r1 = acc[mt][nt][1] + bv.y;
            float r2 = acc[mt][nt][2] + bv.x;
            float r3 = acc[mt][nt][3] + bv.y;
            if (EPI == 0) {
                r0 = 0.5f*r0*(1.f + erff(r0*0.7071067811865476f));
                r1 = 0.5f*r1*(1.f + erff(r1*0.7071067811865476f));
                r2 = 0.5f*r2*(1.f + erff(r2*0.7071067811865476f));
                r3 = 0.5f*r3*(1.f + erff(r3*0.7071067811865476f));
            } else {
                float2 q0 = *(const float2*)&res[gm*Nn + gn];
                float2 q1 = *(const float2*)&res[(gm + 8)*Nn + gn];
                r0 += q0.x; r1 += q0.y; r2 += q1.x; r3 += q1.y;
            }
            *(float2*)&C[gm*Nn + gn]       = make_float2(r0, r1);
            *(float2*)&C[(gm + 8)*Nn + gn] = make_float2(r2, r3);
        }
    }
}

// LayerNorm over (N,C) per batch element; double-precision statistics.
__global__ void k_ln2d(const float* __restrict__ y, const float* __restrict__ g,
                       const float* __restrict__ be, float* __restrict__ xout)
{
    __shared__ double ws[32], wq[32];
    __shared__ float mv[2];
    int b = blockIdx.x;
    const float* yb = y + b*NPT*CC;
    float* xb = xout + b*NPT*CC;
    int t = threadIdx.x;                   // 1024
    double s = 0.0, q = 0.0;
    for (int i = t; i < NPT*CC; i += 1024) { double v = (double)yb[i]; s += v; q += v*v; }
    #pragma unroll
    for (int off = 16; off; off >>= 1) {
        s += __shfl_xor_sync(0xffffffffu, s, off);
        q += __shfl_xor_sync(0xffffffffu, q, off);
    }
    if ((t & 31) == 0) { ws[t >> 5] = s; wq[t >> 5] = q; }
    __syncthreads();
    if (t < 32) {
        s = ws[t]; q = wq[t];
        #pragma unroll
        for (int off = 16; off; off >>= 1) {
            s += __shfl_xor_sync(0xffffffffu, s, off);
            q += __shfl_xor_sync(0xffffffffu, q, off);
        }
        if (t == 0) {
            const double cnt = (double)(NPT*CC);
            double mu = s / cnt;
            double var = q / cnt - mu*mu;
            mv[0] = (float)mu; mv[1] = (float)rsqrt(var + (double)EPSV);
        }
    }
    __syncthreads();
    float mu = mv[0], rs = mv[1];
    for (int i = t; i < NPT*CC; i += 1024)
        xb[i] = (yb[i] - mu)*rs*g[i] + be[i];
}

// ---------------- host ----------------
extern "C" void kernel_launch(void* const* d_in, const int* in_sizes, int n_in,
                              void* d_out, int out_size)
{
    (void)in_sizes; (void)n_in; (void)out_size;
    const float* x_in  = (const float*)d_in[0];
    const float* qw    = (const float*)d_in[1];
    const float* qb    = (const float*)d_in[2];
    const float* kw    = (const float*)d_in[3];
    const float* kb    = (const float*)d_in[4];
    const float* vw    = (const float*)d_in[5];
    const float* vb    = (const float*)d_in[6];
    const float* rw    = (const float*)d_in[7];
    const float* rb    = (const float*)d_in[8];
    const float* bng   = (const float*)d_in[9];
    const float* bnb   = (const float*)d_in[10];
    const float* pw    = (const float*)d_in[11];
    const float* pb    = (const float*)d_in[12];
    const float* l1g   = (const float*)d_in[13];
    const float* l1b   = (const float*)d_in[14];
    const float* w1    = (const float*)d_in[15];
    const float* b1    = (const float*)d_in[16];
    const float* w2    = (const float*)d_in[17];
    const float* b2    = (const float*)d_in[18];
    const float* l2g   = (const float*)d_in[19];
    const float* l2b   = (const float*)d_in[20];

    float *px, *pq, *pk, *pv, *pa, *po, *py, *ph, *pab;
    double *pst;
    cudaGetSymbolAddress((void**)&px,  g_x);
    cudaGetSymbolAddress((void**)&pq,  g_q);
    cudaGetSymbolAddress((void**)&pk,  g_k);
    cudaGetSymbolAddress((void**)&pv,  g_v);
    cudaGetSymbolAddress((void**)&pa,  g_attn);
    cudaGetSymbolAddress((void**)&po,  g_o);
    cudaGetSymbolAddress((void**)&py,  g_y);
    cudaGetSymbolAddress((void**)&ph,  g_h);
    cudaGetSymbolAddress((void**)&pst, g_bnstat);
    cudaGetSymbolAddress((void**)&pab, g_bnab);

    for (int l = 0; l < LLAY; l++) {
        const float* xsrc = (l == 0) ? x_in : px;
        float* ln2dst = (l == LLAY-1) ? (float*)d_out : px;

        k_conv<<<BN_, 256>>>(xsrc,
                             qw + l*81, qb + l*3,
                             kw + l*81, kb + l*3,
                             vw + l*81, vb + l*3,
                             pq, pk, pv);
        k_qk_softmax<<<dim3(NPT/16, BH_), 256>>>(pq, pk, pa);
        k_zero_stat<<<1, 128>>>(pst);
        k_reatten<<<(BB*NPT*NPT)/(256*4), 256>>>(pa, rw + l*HH*HH, rb + l*HH, pst);
        k_bnfinal<<<1, 32>>>(pst, bng + l*HH, bnb + l*HH, pab);
        k_av<<<dim3(NPT/64, BH_), 256>>>(pa, pv, pab, po);
        k_tgemm<1><<<dim3(CC/128, BN_/128), 256>>>(po, pw + l*CC*CC, pb + l*CC, xsrc, py, CC, CC);
        k_ln2d<<<BB, 1024>>>(py, l1g + l*NPT*CC, l1b + l*NPT*CC, px);
        k_tgemm<0><<<dim3(HIDD/128, BN_/128), 256>>>(px, w1 + l*CC*HIDD, b1 + l*HIDD, px, ph, CC, HIDD);
        k_tgemm<1><<<dim3(CC/128, BN_/128), 256>>>(ph, w2 + l*HIDD*CC, b2 + l*CC, px, py, HIDD, CC);
        k_ln2d<<<BB, 1024>>>(py, l2g + l*NPT*CC, l2b + l*NPT*CC, ln2dst);
    }
}

// round 6
// speedup vs baseline: 1.3490x; 1.1983x over previous
#include <cuda_runtime.h>
#include <cuda_bf16.h>
#include <math.h>

#define BB    64
#define NPT   256
#define CHANS 3
#define PPX   16
#define HH    8
#define CC    768
#define HIDD  1536
#define HDIM  96
#define LLAY  5
#define BN_   (BB*NPT)      // 16384
#define BH_   (BB*HH)       // 512
#define EPSV  1e-5f
#define SCL   0.1020620726159657f   // 96^-0.5

#define LOFF  (CC*CC + CC*HIDD + HIDD*CC)   // 2949120 per-layer weight elems

// ---------------- scratch (device globals; no allocation) ----------------
__device__ float  g_x   [BN_*CC];
__device__ float  g_q   [BH_*NPT*HDIM];
__device__ float  g_k   [BH_*NPT*HDIM];
__device__ float  g_v   [BH_*NPT*HDIM];
__device__ float  g_attn[BH_*NPT*NPT];     // 33.55M floats
__device__ float  g_o   [BN_*CC];
__device__ float  g_y   [BN_*CC];
__device__ float  g_h   [BN_*HIDD];
__device__ double g_bnstat[16*8];
__device__ float  g_bnab [2*HH];
__device__ __nv_bfloat16 g_wthi[LLAY*LOFF];   // transposed weights, hi plane
__device__ __nv_bfloat16 g_wtlo[LLAY*LOFF];   // transposed weights, lo plane

// ---------------- kernels ----------------

// 3x3 SAME conv (3->3 ch) on each token image, q/k/v at once. Writes [B,H,N,HD].
__global__ void k_conv(const float* __restrict__ x,
                       const float* __restrict__ qw, const float* __restrict__ qb,
                       const float* __restrict__ kw, const float* __restrict__ kb,
                       const float* __restrict__ vw, const float* __restrict__ vb,
                       float* __restrict__ q, float* __restrict__ k, float* __restrict__ v)
{
    __shared__ float xt[CHANS][PPX][PPX];
    __shared__ float wq[81], wk[81], wv[81];
    int token = blockIdx.x;
    int b = token / NPT, n = token % NPT;
    int t = threadIdx.x;
    for (int i = t; i < CHANS*PPX*PPX; i += 256)
        ((float*)xt)[i] = x[token*CC + i];
    if (t < 81) { wq[t] = qw[t]; wk[t] = kw[t]; wv[t] = vw[t]; }
    __syncthreads();
    int py = t / PPX, px = t % PPX;
    for (int o = 0; o < CHANS; o++) {
        float aq = qb[o], ak = kb[o], av = vb[o];
        #pragma unroll
        for (int i = 0; i < CHANS; i++) {
            #pragma unroll
            for (int dy = 0; dy < 3; dy++) {
                int yy = py + dy - 1;
                if (yy < 0 || yy >= PPX) continue;
                #pragma unroll
                for (int dx = 0; dx < 3; dx++) {
                    int xx = px + dx - 1;
                    if (xx < 0 || xx >= PPX) continue;
                    float xv = xt[i][yy][xx];
                    int wi = ((o*CHANS + i)*3 + dy)*3 + dx;
                    aq += xv * wq[wi];
                    ak += xv * wk[wi];
                    av += xv * wv[wi];
                }
            }
        }
        int f = o*256 + t;
        int h = f / HDIM, d = f % HDIM;
        int idx = ((b*HH + h)*NPT + n)*HDIM + d;
        q[idx] = aq; k[idx] = ak; v[idx] = av;
    }
}

// Fused QK^T * scale + row softmax. grid (N/16, BH), 256 threads.
__global__ void k_qk_softmax(const float* __restrict__ q, const float* __restrict__ k,
                             float* __restrict__ attn)
{
    __shared__ float Ks[256][17];
    __shared__ float Qs[16*HDIM];
    int bh = blockIdx.y;
    int r0 = blockIdx.x * 16;
    int t = threadIdx.x, w = t >> 5, l = t & 31;
    const float* Kb = k + bh*NPT*HDIM;
    const float* Qb = q + (bh*NPT + r0)*HDIM;
    for (int i = t; i < 16*HDIM; i += 256) Qs[i] = Qb[i];

    float s0[8], s1[8];
    #pragma unroll
    for (int j = 0; j < 8; j++) { s0[j] = 0.f; s1[j] = 0.f; }
    int row0 = 2*w, row1 = 2*w + 1;

    for (int d0 = 0; d0 < HDIM; d0 += 16) {
        __syncthreads();
        #pragma unroll
        for (int j = 0; j < 4; j++) {
            int i4 = t + 256*j;
            int r = i4 >> 2, c4 = i4 & 3;
            float4 vv = *(const float4*)&Kb[r*HDIM + d0 + c4*4];
            Ks[r][c4*4+0] = vv.x; Ks[r][c4*4+1] = vv.y;
            Ks[r][c4*4+2] = vv.z; Ks[r][c4*4+3] = vv.w;
        }
        __syncthreads();
        #pragma unroll
        for (int dd = 0; dd < 16; dd++) {
            float q0 = Qs[row0*HDIM + d0 + dd];
            float q1 = Qs[row1*HDIM + d0 + dd];
            #pragma unroll
            for (int j = 0; j < 8; j++) {
                float kv = Ks[l + 32*j][dd];
                s0[j] += q0*kv; s1[j] += q1*kv;
            }
        }
    }
    float m0 = -1e30f, m1 = -1e30f;
    #pragma unroll
    for (int j = 0; j < 8; j++) {
        s0[j] *= SCL; s1[j] *= SCL;
        m0 = fmaxf(m0, s0[j]); m1 = fmaxf(m1, s1[j]);
    }
    #pragma unroll
    for (int off = 16; off; off >>= 1) {
        m0 = fmaxf(m0, __shfl_xor_sync(0xffffffffu, m0, off));
        m1 = fmaxf(m1, __shfl_xor_sync(0xffffffffu, m1, off));
    }
    float sum0 = 0.f, sum1 = 0.f;
    #pragma unroll
    for (int j = 0; j < 8; j++) {
        s0[j] = expf(s0[j] - m0); sum0 += s0[j];
        s1[j] = expf(s1[j] - m1); sum1 += s1[j];
    }
    #pragma unroll
    for (int off = 16; off; off >>= 1) {
        sum0 += __shfl_xor_sync(0xffffffffu, sum0, off);
        sum1 += __shfl_xor_sync(0xffffffffu, sum1, off);
    }
    float inv0 = 1.f / sum0, inv1 = 1.f / sum1;
    float* a0 = attn + (bh*NPT + r0 + row0)*NPT;
    float* a1 = attn + (bh*NPT + r0 + row1)*NPT;
    #pragma unroll
    for (int j = 0; j < 8; j++) {
        a0[l + 32*j] = s0[j]*inv0;
        a1[l + 32*j] = s1[j]*inv1;
    }
}

__global__ void k_zero_stat(double* __restrict__ stat)
{
    int t = threadIdx.x;
    if (t < 16*8) stat[t] = 0.0;
}

// Re-attention (head mixing, in place, float4-vectorized) + BN stats (double).
__global__ void k_reatten(float* __restrict__ attn, const float* __restrict__ rw,
                          const float* __restrict__ rb, double* __restrict__ stat)
{
    __shared__ float srw[64];
    __shared__ float srb[8];
    __shared__ double sacc[16];
    int t = threadIdx.x;
    if (t < 64) srw[t] = rw[t];
    if (t < 8)  srb[t] = rb[t];
    if (t < 16) sacc[t] = 0.0;
    __syncthreads();
    int e = (blockIdx.x*256 + t)*4;
    int b  = e >> 16;
    int nm = e & 65535;
    int base = b*HH*65536 + nm;
    float4 a[HH];
    #pragma unroll
    for (int h = 0; h < HH; h++) a[h] = *(const float4*)&attn[base + h*65536];
    float4 o[HH];
    #pragma unroll
    for (int oo = 0; oo < HH; oo++) {
        float bias = srb[oo];
        float sx = bias, sy = bias, sz = bias, sw = bias;
        #pragma unroll
        for (int i = 0; i < HH; i++) {
            float w = srw[oo*HH + i];
            sx += w*a[i].x; sy += w*a[i].y; sz += w*a[i].z; sw += w*a[i].w;
        }
        o[oo] = make_float4(sx, sy, sz, sw);
    }
    #pragma unroll
    for (int h = 0; h < HH; h++) *(float4*)&attn[base + h*65536] = o[h];
    #pragma unroll
    for (int h = 0; h < HH; h++) {
        float fs = o[h].x + o[h].y + o[h].z + o[h].w;
        float fq = o[h].x*o[h].x + o[h].y*o[h].y + o[h].z*o[h].z + o[h].w*o[h].w;
        double s = (double)fs, qq = (double)fq;
        #pragma unroll
        for (int off = 16; off; off >>= 1) {
            s  += __shfl_xor_sync(0xffffffffu, s, off);
            qq += __shfl_xor_sync(0xffffffffu, qq, off);
        }
        if ((t & 31) == 0) { atomicAdd(&sacc[h], s); atomicAdd(&sacc[8+h], qq); }
    }
    __syncthreads();
    if (t < 16) atomicAdd(&stat[t*8], sacc[t]);
}

__global__ void k_bnfinal(const double* __restrict__ stat, const float* __restrict__ bg,
                          const float* __restrict__ bb_, float* __restrict__ ab)
{
    int h = threadIdx.x;
    if (h >= HH) return;
    const double cnt = (double)BB * (double)NPT * (double)NPT;
    double mu  = stat[h*8] / cnt;
    double var = stat[(8+h)*8] / cnt - mu*mu;
    float  al  = (float)(rsqrt(var + (double)EPSV) * (double)bg[h]);
    ab[h]      = al;
    ab[HH + h] = bb_[h] - (float)mu * al;
}

// O = (alpha*attnR+beta) @ V; writes [B,N,C]. grid (N/64, BH), 256 threads.
__global__ void k_av(const float* __restrict__ attn, const float* __restrict__ v,
                     const float* __restrict__ ab, float* __restrict__ o)
{
    __shared__ float As[64][33];
    __shared__ float Vs[32][96];
    int bh = blockIdx.y;
    int n0 = blockIdx.x * 64;
    int t = threadIdx.x;
    int tx = t & 31, ty = t >> 5;
    int b = bh / HH, h = bh % HH;
    float alpha = ab[h], beta = ab[HH + h];
    float acc[8][3];
    #pragma unroll
    for (int i = 0; i < 8; i++) { acc[i][0] = 0.f; acc[i][1] = 0.f; acc[i][2] = 0.f; }
    const float* Ab = attn + (bh*NPT + n0)*NPT;
    const float* Vb = v + bh*NPT*HDIM;

    for (int k0 = 0; k0 < NPT; k0 += 32) {
        #pragma unroll
        for (int j = 0; j < 2; j++) {
            int i4 = t + 256*j;
            int r = i4 >> 3, c4 = i4 & 7;
            float4 vv = *(const float4*)&Ab[r*NPT + k0 + c4*4];
            As[r][c4*4+0] = alpha*vv.x + beta;
            As[r][c4*4+1] = alpha*vv.y + beta;
            As[r][c4*4+2] = alpha*vv.z + beta;
            As[r][c4*4+3] = alpha*vv.w + beta;
        }
        #pragma unroll
        for (int j = 0; j < 12; j++) {
            int i = t + 256*j;
            int r = i / 96, c = i % 96;
            Vs[r][c] = Vb[(k0 + r)*HDIM + c];
        }
        __syncthreads();
        #pragma unroll
        for (int kk = 0; kk < 32; kk++) {
            float v0 = Vs[kk][3*tx], v1 = Vs[kk][3*tx+1], v2 = Vs[kk][3*tx+2];
            #pragma unroll
            for (int i = 0; i < 8; i++) {
                float a = As[ty*8 + i][kk];
                acc[i][0] += a*v0; acc[i][1] += a*v1; acc[i][2] += a*v2;
            }
        }
        __syncthreads();
    }
    #pragma unroll
    for (int i = 0; i < 8; i++) {
        int gn = n0 + ty*8 + i;
        float* op = o + (b*NPT + gn)*CC + h*HDIM + 3*tx;
        op[0] = acc[i][0];
        op[1] = acc[i][1];
        op[2] = acc[i][2];
    }
}

// ---------------- weight transpose + bf16 hi/lo split (once per launch) ------
// W[K][N] row-major -> th/tl[N][K] bf16.
__global__ void k_wsplit(const float* __restrict__ W,
                         __nv_bfloat16* __restrict__ th, __nv_bfloat16* __restrict__ tl,
                         int K, int N)
{
    __shared__ float tile[32][33];
    int n0 = blockIdx.x * 32, k0 = blockIdx.y * 32;
    int tx = threadIdx.x & 31, ty = threadIdx.x >> 5;   // 256 threads
    #pragma unroll
    for (int j = 0; j < 4; j++)
        tile[ty + j*8][tx] = W[(k0 + ty + j*8)*N + n0 + tx];
    __syncthreads();
    #pragma unroll
    for (int j = 0; j < 4; j++) {
        float x = tile[tx][ty + j*8];            // W[k0+tx][n0+ty+j*8]
        __nv_bfloat16 h = __float2bfloat16(x);
        __nv_bfloat16 lo = __float2bfloat16(x - __bfloat162float(h));
        th[(n0 + ty + j*8)*K + k0 + tx] = h;
        tl[(n0 + ty + j*8)*K + k0 + tx] = lo;
    }
}

// ---------------- bf16 split tensor-core GEMM ----------------
// C[M,N] = A[M,K] @ B[K,N] (+epilogue). B supplied pre-transposed/pre-split.
// x = hi + lo (bf16 each); A*B = Ahi*Bhi + Ahi*Blo + Alo*Bhi.
// Block 128x128x32, 256 threads, warp tile 64x32, mma.sync.m16n8k16.bf16.
// Smem word layout [row][16] u32 (bf16x2), column = 4*(w&3) + ((w>>2) ^ 2*((row>>1)&1))
// -> conflict-free 8B fragment loads, no padding.
__device__ __forceinline__ void splitpack(float x, float y, unsigned& h, unsigned& l)
{
    __nv_bfloat16 hx = __float2bfloat16(x), hy = __float2bfloat16(y);
    __nv_bfloat16 lx = __float2bfloat16(x - __bfloat162float(hx));
    __nv_bfloat16 ly = __float2bfloat16(y - __bfloat162float(hy));
    unsigned short ux, uy;
    *(__nv_bfloat16*)&ux = hx; *(__nv_bfloat16*)&uy = hy;
    h = (unsigned)ux | ((unsigned)uy << 16);
    *(__nv_bfloat16*)&ux = lx; *(__nv_bfloat16*)&uy = ly;
    l = (unsigned)ux | ((unsigned)uy << 16);
}

#define MMA_BF16(ACC, A0, A1, A2, A3, B0, B1)                                 \
    asm volatile(                                                             \
        "mma.sync.aligned.m16n8k16.row.col.f32.bf16.bf16.f32 "                \
        "{%0,%1,%2,%3}, {%4,%5,%6,%7}, {%8,%9}, {%0,%1,%2,%3};"               \
        : "+f"((ACC)[0]), "+f"((ACC)[1]), "+f"((ACC)[2]), "+f"((ACC)[3])      \
        : "r"(A0), "r"(A1), "r"(A2), "r"(A3), "r"(B0), "r"(B1))

template<int EPI>
__global__ void __launch_bounds__(256, 2)
k_bgemm(const float* __restrict__ A,
        const __nv_bfloat16* __restrict__ BtH, const __nv_bfloat16* __restrict__ BtL,
        const float* __restrict__ bias, const float* __restrict__ res,
        float* __restrict__ C, int K, int Nn)
{
    __shared__ unsigned AsH[128][16], AsL[128][16];
    __shared__ unsigned BsH[128][16], BsL[128][16];
    int m0 = blockIdx.y * 128, n0 = blockIdx.x * 128;
    int t = threadIdx.x;
    int wid = t >> 5, l = t & 31, gid = l >> 2, tid4 = l & 3;
    int wm = (wid & 1) * 64, wn = (wid >> 1) * 32;
    int gc = (gid >> 1) & 1;                 // fragment-row swizzle selector

    float acc[4][4][4];
    #pragma unroll
    for (int mt = 0; mt < 4; mt++)
        #pragma unroll
        for (int nt = 0; nt < 4; nt++)
            #pragma unroll
            for (int r = 0; r < 4; r++) acc[mt][nt][r] = 0.f;

    for (int k0 = 0; k0 < K; k0 += 32) {
        // ---- stage A (128x32 fp32 -> hi/lo bf16x2 words) ----
        #pragma unroll
        for (int i = 0; i < 4; i++) {
            int m = i*32 + (t >> 3), f4 = t & 7;
            float4 v = *(const float4*)&A[(size_t)(m0 + m)*K + k0 + f4*4];
            unsigned c2 = ((m >> 1) & 1) << 1;
            int w0 = f4*2;
            unsigned h0, l0, h1, l1;
            splitpack(v.x, v.y, h0, l0);
            splitpack(v.z, v.w, h1, l1);
            int col0 = 4*(w0 & 3)      + ((w0 >> 2) ^ c2);
            int col1 = 4*((w0+1) & 3)  + (((w0+1) >> 2) ^ c2);
            AsH[m][col0] = h0; AsL[m][col0] = l0;
            AsH[m][col1] = h1; AsL[m][col1] = l1;
        }
        // ---- stage B (pre-split bf16, 128x32) ----
        {
            int n = t >> 1, h = t & 1;
            const uint4* sh = (const uint4*)(BtH + (size_t)(n0 + n)*K + k0 + h*16);
            const uint4* sl = (const uint4*)(BtL + (size_t)(n0 + n)*K + k0 + h*16);
            uint4 uh0 = sh[0], uh1 = sh[1], ul0 = sl[0], ul1 = sl[1];
            unsigned c2 = ((n >> 1) & 1) << 1;
            const unsigned* ph0 = (const unsigned*)&uh0;
            const unsigned* ph1 = (const unsigned*)&uh1;
            const unsigned* pl0 = (const unsigned*)&ul0;
            const unsigned* pl1 = (const unsigned*)&ul1;
            #pragma unroll
            for (int i = 0; i < 4; i++) {
                int colA = 4*i + ((2*h)     ^ c2);   // words h*8 + i
                int colB = 4*i + ((2*h + 1) ^ c2);   // words h*8 + 4 + i
                BsH[n][colA] = ph0[i]; BsL[n][colA] = pl0[i];
                BsH[n][colB] = ph1[i]; BsL[n][colB] = pl1[i];
            }
        }
        __syncthreads();
        #pragma unroll
        for (int ks = 0; ks < 2; ks++) {
            int cb = 4*tid4 + 2*(ks ^ gc);
            uint2 bh[4], bl[4];
            #pragma unroll
            for (int nt = 0; nt < 4; nt++) {
                int cn = wn + nt*8 + gid;
                bh[nt] = *(const uint2*)&BsH[cn][cb];
                bl[nt] = *(const uint2*)&BsL[cn][cb];
            }
            #pragma unroll
            for (int mt = 0; mt < 4; mt++) {
                int r0 = wm + mt*16 + gid, r1 = r0 + 8;
                uint2 ah0 = *(const uint2*)&AsH[r0][cb];
                uint2 ah1 = *(const uint2*)&AsH[r1][cb];
                uint2 al0 = *(const uint2*)&AsL[r0][cb];
                uint2 al1 = *(const uint2*)&AsL[r1][cb];
                #pragma unroll
                for (int nt = 0; nt < 4; nt++) {
                    MMA_BF16(acc[mt][nt], ah0.x, ah1.x, ah0.y, ah1.y, bl[nt].x, bl[nt].y);
                    MMA_BF16(acc[mt][nt], al0.x, al1.x, al0.y, al1.y, bh[nt].x, bh[nt].y);
                    MMA_BF16(acc[mt][nt], ah0.x, ah1.x, ah0.y, ah1.y, bh[nt].x, bh[nt].y);
                }
            }
        }
        __syncthreads();
    }

    #pragma unroll
    for (int mt = 0; mt < 4; mt++) {
        #pragma unroll
        for (int nt = 0; nt < 4; nt++) {
            int gm = m0 + wm + mt*16 + gid;
            int gn = n0 + wn + nt*8 + tid4*2;
            float2 bv = *(const float2*)&bias[gn];
            float r0 = acc[mt][nt][0] + bv.x;
            float r1 = acc[mt][nt][1] + bv.y;
            float r2 = acc[mt][nt][2] + bv.x;
            float r3 = acc[mt][nt][3] + bv.y;
            if (EPI == 0) {
                r0 = 0.5f*r0*(1.f + erff(r0*0.7071067811865476f));
                r1 = 0.5f*r1*(1.f + erff(r1*0.7071067811865476f));
                r2 = 0.5f*r2*(1.f + erff(r2*0.7071067811865476f));
                r3 = 0.5f*r3*(1.f + erff(r3*0.7071067811865476f));
            } else {
                float2 q0 = *(const float2*)&res[gm*Nn + gn];
                float2 q1 = *(const float2*)&res[(gm + 8)*Nn + gn];
                r0 += q0.x; r1 += q0.y; r2 += q1.x; r3 += q1.y;
            }
            *(float2*)&C[gm*Nn + gn]       = make_float2(r0, r1);
            *(float2*)&C[(gm + 8)*Nn + gn] = make_float2(r2, r3);
        }
    }
}

// LayerNorm over (N,C) per batch element; double-precision statistics.
__global__ void k_ln2d(const float* __restrict__ y, const float* __restrict__ g,
                       const float* __restrict__ be, float* __restrict__ xout)
{
    __shared__ double ws[32], wq[32];
    __shared__ float mv[2];
    int b = blockIdx.x;
    const float* yb = y + b*NPT*CC;
    float* xb = xout + b*NPT*CC;
    int t = threadIdx.x;
    double s = 0.0, q = 0.0;
    for (int i = t; i < NPT*CC; i += 1024) { double v = (double)yb[i]; s += v; q += v*v; }
    #pragma unroll
    for (int off = 16; off; off >>= 1) {
        s += __shfl_xor_sync(0xffffffffu, s, off);
        q += __shfl_xor_sync(0xffffffffu, q, off);
    }
    if ((t & 31) == 0) { ws[t >> 5] = s; wq[t >> 5] = q; }
    __syncthreads();
    if (t < 32) {
        s = ws[t]; q = wq[t];
        #pragma unroll
        for (int off = 16; off; off >>= 1) {
            s += __shfl_xor_sync(0xffffffffu, s, off);
            q += __shfl_xor_sync(0xffffffffu, q, off);
        }
        if (t == 0) {
            const double cnt = (double)(NPT*CC);
            double mu = s / cnt;
            double var = q / cnt - mu*mu;
            mv[0] = (float)mu; mv[1] = (float)rsqrt(var + (double)EPSV);
        }
    }
    __syncthreads();
    float mu = mv[0], rs = mv[1];
    for (int i = t; i < NPT*CC; i += 1024)
        xb[i] = (yb[i] - mu)*rs*g[i] + be[i];
}

// ---------------- host ----------------
extern "C" void kernel_launch(void* const* d_in, const int* in_sizes, int n_in,
                              void* d_out, int out_size)
{
    (void)in_sizes; (void)n_in; (void)out_size;
    const float* x_in  = (const float*)d_in[0];
    const float* qw    = (const float*)d_in[1];
    const float* qb    = (const float*)d_in[2];
    const float* kw    = (const float*)d_in[3];
    const float* kb    = (const float*)d_in[4];
    const float* vw    = (const float*)d_in[5];
    const float* vb    = (const float*)d_in[6];
    const float* rw    = (const float*)d_in[7];
    const float* rb    = (const float*)d_in[8];
    const float* bng   = (const float*)d_in[9];
    const float* bnb   = (const float*)d_in[10];
    const float* pw    = (const float*)d_in[11];
    const float* pb    = (const float*)d_in[12];
    const float* l1g   = (const float*)d_in[13];
    const float* l1b   = (const float*)d_in[14];
    const float* w1    = (const float*)d_in[15];
    const float* b1    = (const float*)d_in[16];
    const float* w2    = (const float*)d_in[17];
    const float* b2    = (const float*)d_in[18];
    const float* l2g   = (const float*)d_in[19];
    const float* l2b   = (const float*)d_in[20];

    float *px, *pq, *pk, *pv, *pa, *po, *py, *ph, *pab;
    double *pst;
    __nv_bfloat16 *pwh, *pwl;
    cudaGetSymbolAddress((void**)&px,  g_x);
    cudaGetSymbolAddress((void**)&pq,  g_q);
    cudaGetSymbolAddress((void**)&pk,  g_k);
    cudaGetSymbolAddress((void**)&pv,  g_v);
    cudaGetSymbolAddress((void**)&pa,  g_attn);
    cudaGetSymbolAddress((void**)&po,  g_o);
    cudaGetSymbolAddress((void**)&py,  g_y);
    cudaGetSymbolAddress((void**)&ph,  g_h);
    cudaGetSymbolAddress((void**)&pst, g_bnstat);
    cudaGetSymbolAddress((void**)&pab, g_bnab);
    cudaGetSymbolAddress((void**)&pwh, g_wthi);
    cudaGetSymbolAddress((void**)&pwl, g_wtlo);

    // pre-split + transpose all weights (bf16 hi/lo planes)
    for (int l = 0; l < LLAY; l++) {
        size_t base = (size_t)l * LOFF;
        k_wsplit<<<dim3(CC/32,   CC/32),   256>>>(pw + (size_t)l*CC*CC,
                                                  pwh + base, pwl + base, CC, CC);
        k_wsplit<<<dim3(HIDD/32, CC/32),   256>>>(w1 + (size_t)l*CC*HIDD,
                                                  pwh + base + CC*CC, pwl + base + CC*CC, CC, HIDD);
        k_wsplit<<<dim3(CC/32,   HIDD/32), 256>>>(w2 + (size_t)l*HIDD*CC,
                                                  pwh + base + CC*CC + CC*HIDD,
                                                  pwl + base + CC*CC + CC*HIDD, HIDD, CC);
    }

    for (int l = 0; l < LLAY; l++) {
        const float* xsrc = (l == 0) ? x_in : px;
        float* ln2dst = (l == LLAY-1) ? (float*)d_out : px;
        size_t base = (size_t)l * LOFF;
        const __nv_bfloat16* pjH = pwh + base;
        const __nv_bfloat16* pjL = pwl + base;
        const __nv_bfloat16* f1H = pwh + base + CC*CC;
        const __nv_bfloat16* f1L = pwl + base + CC*CC;
        const __nv_bfloat16* f2H = pwh + base + CC*CC + CC*HIDD;
        const __nv_bfloat16* f2L = pwl + base + CC*CC + CC*HIDD;

        k_conv<<<BN_, 256>>>(xsrc,
                             qw + l*81, qb + l*3,
                             kw + l*81, kb + l*3,
                             vw + l*81, vb + l*3,
                             pq, pk, pv);
        k_qk_softmax<<<dim3(NPT/16, BH_), 256>>>(pq, pk, pa);
        k_zero_stat<<<1, 128>>>(pst);
        k_reatten<<<(BB*NPT*NPT)/(256*4), 256>>>(pa, rw + l*HH*HH, rb + l*HH, pst);
        k_bnfinal<<<1, 32>>>(pst, bng + l*HH, bnb + l*HH, pab);
        k_av<<<dim3(NPT/64, BH_), 256>>>(pa, pv, pab, po);
        k_bgemm<1><<<dim3(CC/128, BN_/128), 256>>>(po, pjH, pjL, pb + l*CC, xsrc, py, CC, CC);
        k_ln2d<<<BB, 1024>>>(py, l1g + l*NPT*CC, l1b + l*NPT*CC, px);
        k_bgemm<0><<<dim3(HIDD/128, BN_/128), 256>>>(px, f1H, f1L, b1 + l*HIDD, px, ph, CC, HIDD);
        k_bgemm<1><<<dim3(CC/128, BN_/128), 256>>>(ph, f2H, f2L, b2 + l*CC, px, py, HIDD, CC);
        k_ln2d<<<BB, 1024>>>(py, l2g + l*NPT*CC, l2b + l*NPT*CC, ln2dst);
    }
}